// round 13
// baseline (speedup 1.0000x reference)
#include <cuda_runtime.h>
#include <math.h>

// Problem constants
#define B_TOT 256
#define AIN   8
#define MUL   1024
#define NK    20
#define NO    16

// Persistent scratch (device globals; allocation-free)
__device__ __align__(16) float g_c[NK * MUL];
__device__ __align__(16) float g_b[NK * MUL];
__device__ __align__(16) float g_bpart[16 * NK * MUL];
__device__ __align__(16) float g_wv[B_TOT * NK * AIN];
__device__ __align__(16) float g_xsum[B_TOT * AIN];

// Packed f32x2 FMA
#define FMA2(acc, a, b) \
    asm("fma.rn.f32x2 %0, %1, %2, %0;" : "+l"(acc) : "l"(a), "l"(b))

__device__ __forceinline__ float pair_sum(unsigned long long u) {
    float lo = __uint_as_float((unsigned)(u & 0xffffffffu));
    float hi = __uint_as_float((unsigned)(u >> 32));
    return lo + hi;
}

// ---------------------------------------------------------------------------
// prep_xsum (R12): g_xsum[b][a] = sum_m x[b][m][a].
// ---------------------------------------------------------------------------
__global__ void __launch_bounds__(256)
prep_xsum(const float* __restrict__ x)
{
    __shared__ float red[8][8];
    const int t = threadIdx.x;
    const int b = blockIdx.x;
    const int w = t >> 5, lane = t & 31;

    const float4* xs4 = (const float4*)(x + (size_t)b * 8192);
    float4 acc = make_float4(0.f, 0.f, 0.f, 0.f);
    #pragma unroll
    for (int i = 0; i < 8; i++) {
        float4 v = xs4[t + i * 256];
        acc.x += v.x; acc.y += v.y; acc.z += v.z; acc.w += v.w;
    }
    #pragma unroll
    for (int off = 2; off <= 16; off <<= 1) {
        acc.x += __shfl_xor_sync(0xffffffffu, acc.x, off);
        acc.y += __shfl_xor_sync(0xffffffffu, acc.y, off);
        acc.z += __shfl_xor_sync(0xffffffffu, acc.z, off);
        acc.w += __shfl_xor_sync(0xffffffffu, acc.w, off);
    }
    if (lane < 2) {
        red[w][lane * 4 + 0] = acc.x;
        red[w][lane * 4 + 1] = acc.y;
        red[w][lane * 4 + 2] = acc.z;
        red[w][lane * 4 + 3] = acc.w;
    }
    __syncthreads();
    if (t < 8) {
        float s = 0.f;
        #pragma unroll
        for (int i = 0; i < 8; i++) s += red[i][t];
        g_xsum[b * 8 + t] = s;
    }
}

// ---------------------------------------------------------------------------
// u0_kernel (R12): iteration-0 fused (y0 from xsum, tail, agree partials).
// ---------------------------------------------------------------------------
#define U_THREADS 320

__global__ void __launch_bounds__(U_THREADS)
u0_kernel(const float* __restrict__ x, const float* __restrict__ W)
{
    __shared__ float wvs[16 * 160];
    __shared__ float svm[16 * 320];
    __shared__ float ysm[16 * 8];
    __shared__ float cqm[16 * 16];
    float* xsU = svm;

    const int tid   = threadIdx.x;
    const int m0    = blockIdx.x * 64;
    const int bbase = blockIdx.y * 16;

    if (tid < 128) {
        int bb = tid >> 3, a = tid & 7;
        ysm[tid] = g_xsum[(bbase + bb) * 8 + a] * (1.0f / 1024.0f);
    }
    __syncthreads();

    {
        float wreg[8];
        const float4* wp4 = (const float4*)(W + tid * 8);
        float4 wA = wp4[0], wB = wp4[1];
        wreg[0] = wA.x; wreg[1] = wA.y; wreg[2] = wA.z; wreg[3] = wA.w;
        wreg[4] = wB.x; wreg[5] = wB.y; wreg[6] = wB.z; wreg[7] = wB.w;
        #pragma unroll
        for (int bb = 0; bb < 16; bb++) {
            const float* y = ysm + bb * 8;
            float s = 0.f;
            #pragma unroll
            for (int a = 0; a < 8; a++) s += wreg[a] * y[a];
            svm[bb * 320 + tid] = s;
        }
    }
    __syncthreads();

    if (tid < 256) {
        int bb = tid >> 4, o = tid & 15;
        float msq = 0.f;
        #pragma unroll
        for (int kk = 0; kk < NK; kk++) {
            float t = svm[bb * 320 + kk * 16 + o];
            msq += t * t;
        }
        cqm[tid] = msq / ((1.f + msq) * sqrtf(msq));
    }
    __syncthreads();

    {
        const int o = tid & 15;
        #pragma unroll
        for (int bb = 0; bb < 16; bb++)
            svm[bb * 320 + tid] *= cqm[bb * 16 + o];
    }
    __syncthreads();

    {
        const int r   = tid % 160;
        const int bb0 = tid / 160;
        const int kk  = r >> 3, aa = r & 7;
        float w16[16];
        #pragma unroll
        for (int oo = 0; oo < 16; oo++) w16[oo] = W[(kk * 16 + oo) * 8 + aa];
        #pragma unroll
        for (int s8 = 0; s8 < 8; s8++) {
            int bb = bb0 + s8 * 2;
            float acc = 0.f;
            #pragma unroll
            for (int oo = 0; oo < 16; oo++)
                acc += w16[oo] * svm[bb * 320 + kk * 16 + oo];
            wvs[bb * 160 + r] = acc;
        }
    }

    const int mi4 = tid / NK;
    const int k   = tid % NK;
    unsigned long long acc[4];
    #pragma unroll
    for (int i = 0; i < 4; i++) acc[i] = 0ull;

    for (int c0 = 0; c0 < 16; c0 += 8) {
        __syncthreads();
        for (int i = tid; i < 1024; i += U_THREADS) {
            int bi = i >> 7, rr = i & 127;
            ((float4*)(xsU + bi * 512))[rr] =
                ((const float4*)(x + (size_t)(bbase + c0 + bi) * 8192 + m0 * 8))[rr];
        }
        __syncthreads();

        #pragma unroll
        for (int bi = 0; bi < 8; bi++) {
            const ulonglong2* wp = (const ulonglong2*)(wvs + (c0 + bi) * 160 + k * 8);
            ulonglong2 wA = wp[0], wB = wp[1];
            const ulonglong2* xp = (const ulonglong2*)(xsU + bi * 512 + mi4 * 32);
            #pragma unroll
            for (int mm = 0; mm < 4; mm++) {
                ulonglong2 xA = xp[mm * 2];
                ulonglong2 xB = xp[mm * 2 + 1];
                FMA2(acc[mm], xA.x, wA.x);
                FMA2(acc[mm], xA.y, wA.y);
                FMA2(acc[mm], xB.x, wB.x);
                FMA2(acc[mm], xB.y, wB.y);
            }
        }
    }

    float* dst = g_bpart + (size_t)blockIdx.y * (NK * MUL) + k * MUL + m0 + mi4 * 4;
    #pragma unroll
    for (int mm = 0; mm < 4; mm++) dst[mm] = pair_sum(acc[mm]) * (1.0f / 256.0f);
}

// ---------------------------------------------------------------------------
// F kernel v2: 256 blocks (one batch each), 320 threads = (mg in 16, k in 20).
// No transpose, no shuffles. y-partials per thread (64 m's, all 8 atoms) via
// FMA2 with in-register c duplication; smem partial reduce; tail in-block.
// ---------------------------------------------------------------------------
__global__ void __launch_bounds__(320)
fused2_kernel(const float* __restrict__ x, const float* __restrict__ W,
              float* __restrict__ out, int final_iter)
{
    __shared__ float xs[8192];        // x[b] natural [m][a]  32 KB
    __shared__ float ps[16 * 160];    // partials [mg][k*8+a] 10 KB
    __shared__ float ysm[160];
    __shared__ float svm[320];
    __shared__ float cqm[16];

    const int tid = threadIdx.x;
    const int b   = blockIdx.x;

    // stage x: pure coalesced float4 copy (no transpose)
    {
        const float4* xsrc = (const float4*)(x + (size_t)b * 8192);
        #pragma unroll 2
        for (int i = tid; i < 2048; i += 320)
            ((float4*)xs)[i] = xsrc[i];
    }
    __syncthreads();

    // y phase: thread = (mg, k); sum 64 m's for all 8 atoms
    {
        const int mg = tid / 20, k = tid % 20;
        const float* xb = xs + mg * 512;               // 64 m * 8 a
        const float4* crow = (const float4*)(g_c + k * MUL + mg * 64);

        unsigned long long a01 = 0ull, a23 = 0ull, a45 = 0ull, a67 = 0ull;
        #pragma unroll 4
        for (int j = 0; j < 16; j++) {
            float4 c4 = crow[j];
            #pragma unroll
            for (int t = 0; t < 4; t++) {
                unsigned cu = __float_as_uint(t == 0 ? c4.x : t == 1 ? c4.y :
                                              t == 2 ? c4.z : c4.w);
                unsigned long long cv =
                    (unsigned long long)cu | ((unsigned long long)cu << 32);
                const ulonglong2* xp = (const ulonglong2*)(xb + (j * 4 + t) * 8);
                ulonglong2 xA = xp[0];
                ulonglong2 xB = xp[1];
                FMA2(a01, xA.x, cv);
                FMA2(a23, xA.y, cv);
                FMA2(a45, xB.x, cv);
                FMA2(a67, xB.y, cv);
            }
        }
        ulonglong2* pd = (ulonglong2*)(ps + mg * 160 + k * 8);
        pd[0] = make_ulonglong2(a01, a23);
        pd[1] = make_ulonglong2(a45, a67);
    }
    __syncthreads();

    // reduce 16 m-group partials -> y[k][a]
    if (tid < 160) {
        float s = 0.f;
        #pragma unroll
        for (int mg = 0; mg < 16; mg++) s += ps[mg * 160 + tid];
        ysm[tid] = s;
    }
    __syncthreads();

    // tail: s = W y, squash (class-sum per reference), v, wv/out
    const int k = tid >> 4, o = tid & 15;
    {
        const float* wk = W + tid * 8;
        const float* yk = ysm + k * 8;
        float s = 0.f;
        #pragma unroll
        for (int a = 0; a < 8; a++) s += wk[a] * yk[a];
        svm[tid] = s;
        __syncthreads();

        if (tid < NO) {
            float msq = 0.f;
            #pragma unroll
            for (int kk = 0; kk < NK; kk++) {
                float t = svm[kk * NO + tid];
                msq += t * t;
            }
            cqm[tid] = msq / ((1.f + msq) * sqrtf(msq));
        }
        __syncthreads();

        float v = cqm[o] * s;
        if (final_iter) {
            out[(size_t)b * 320 + tid] = v;           // coalesced
        } else {
            svm[tid] = v;
            __syncthreads();
            if (tid < 160) {
                int kk = tid >> 3, aa = tid & 7;
                float acc = 0.f;
                #pragma unroll
                for (int oo = 0; oo < 16; oo++)
                    acc += W[(kk * 16 + oo) * 8 + aa] * svm[kk * 16 + oo];
                g_wv[(size_t)b * 160 + tid] = acc;
            }
        }
    }
}

// ---------------------------------------------------------------------------
// Update kernel (unchanged).
// ---------------------------------------------------------------------------
__global__ void __launch_bounds__(U_THREADS)
update_kernel(const float* __restrict__ x)
{
    __shared__ float xsU[8 * 512];
    __shared__ float wvs[8 * 160];

    const int tid   = threadIdx.x;
    const int m0    = blockIdx.x * 64;
    const int bbase = blockIdx.y * 16;
    const int mi4   = tid / NK;
    const int k     = tid % NK;

    unsigned long long acc[4];
    #pragma unroll
    for (int i = 0; i < 4; i++) acc[i] = 0ull;

    for (int c0 = 0; c0 < 16; c0 += 8) {
        __syncthreads();
        for (int i = tid; i < 1024; i += U_THREADS) {
            int bi = i >> 7, rr = i & 127;
            ((float4*)(xsU + bi * 512))[rr] =
                ((const float4*)(x + (size_t)(bbase + c0 + bi) * 8192 + m0 * 8))[rr];
        }
        for (int i = tid; i < 320; i += U_THREADS) {
            int bi = i / 40, rr = i % 40;
            ((float4*)(wvs + bi * 160))[rr] =
                ((const float4*)(g_wv + (size_t)(bbase + c0 + bi) * 160))[rr];
        }
        __syncthreads();

        #pragma unroll
        for (int bi = 0; bi < 8; bi++) {
            const ulonglong2* wp = (const ulonglong2*)(wvs + bi * 160 + k * 8);
            ulonglong2 wA = wp[0], wB = wp[1];
            const ulonglong2* xp = (const ulonglong2*)(xsU + bi * 512 + mi4 * 32);
            #pragma unroll
            for (int mm = 0; mm < 4; mm++) {
                ulonglong2 xA = xp[mm * 2];
                ulonglong2 xB = xp[mm * 2 + 1];
                FMA2(acc[mm], xA.x, wA.x);
                FMA2(acc[mm], xA.y, wA.y);
                FMA2(acc[mm], xB.x, wB.x);
                FMA2(acc[mm], xB.y, wB.y);
            }
        }
    }

    float* dst = g_bpart + (size_t)blockIdx.y * (NK * MUL) + k * MUL + m0 + mi4 * 4;
    #pragma unroll
    for (int mm = 0; mm < 4; mm++) dst[mm] = pair_sum(acc[mm]) * (1.0f / 256.0f);
}

// ---------------------------------------------------------------------------
// Softmax kernel (no max subtraction; inputs bounded, fp32-safe).
// ---------------------------------------------------------------------------
__global__ void __launch_bounds__(1024)
softmax_kernel(int accum)
{
    const int k = blockIdx.x;
    const int t = threadIdx.x;
    const int lane = t & 31, wp = t >> 5;
    __shared__ float red[32];
    __shared__ float bc;

    float b = accum ? g_b[k * MUL + t] : 0.f;
    #pragma unroll
    for (int p = 0; p < 16; p++) b += g_bpart[p * NK * MUL + k * MUL + t];
    g_b[k * MUL + t] = b;

    float e = expf(b);
    float s = e;
    #pragma unroll
    for (int off = 16; off; off >>= 1)
        s += __shfl_xor_sync(0xffffffffu, s, off);
    if (lane == 0) red[wp] = s;
    __syncthreads();
    if (t < 32) {
        float ss = red[t];
        #pragma unroll
        for (int off = 16; off; off >>= 1)
            ss += __shfl_xor_sync(0xffffffffu, ss, off);
        if (t == 0) bc = ss;
    }
    __syncthreads();

    g_c[k * MUL + t] = e * (1.0f / bc);
}

// ---------------------------------------------------------------------------
extern "C" void kernel_launch(void* const* d_in, const int* in_sizes, int n_in,
                              void* d_out, int out_size)
{
    const float* x = (const float*)d_in[0];   // [256][1024][8] flat view
    const float* W = (const float*)d_in[1];   // [20][16][8]
    float* out = (float*)d_out;               // [256][20][16][1]

    dim3 ugrid(16, 16);

    // iteration 0: xsum -> (y0 + tail + agree) -> softmax
    prep_xsum<<<B_TOT, 256>>>(x);
    u0_kernel<<<ugrid, U_THREADS>>>(x, W);
    softmax_kernel<<<NK, 1024>>>(0);

    // iteration 1
    fused2_kernel<<<B_TOT, 320>>>(x, W, out, 0);
    update_kernel<<<ugrid, U_THREADS>>>(x);
    softmax_kernel<<<NK, 1024>>>(1);

    // iteration 2 (final -> write v)
    fused2_kernel<<<B_TOT, 320>>>(x, W, out, 1);
}

// round 14
// speedup vs baseline: 1.0052x; 1.0052x over previous
#include <cuda_runtime.h>
#include <math.h>

// Problem constants
#define B_TOT 256
#define AIN   8
#define MUL   1024
#define NK    20
#define NO    16

// Persistent scratch (device globals; allocation-free)
__device__ __align__(16) float g_c[NK * MUL];
__device__ __align__(16) float g_b[NK * MUL];
__device__ __align__(16) float g_bpart[16 * NK * MUL];
__device__ __align__(16) float g_xsum[B_TOT * AIN];
__device__ __align__(16) float g_yh[B_TOT * 2 * NK * AIN];   // y partials [b][mh][k][a]

// Packed f32x2 FMA
#define FMA2(acc, a, b) \
    asm("fma.rn.f32x2 %0, %1, %2, %0;" : "+l"(acc) : "l"(a), "l"(b))

__device__ __forceinline__ float pair_sum(unsigned long long u) {
    float lo = __uint_as_float((unsigned)(u & 0xffffffffu));
    float hi = __uint_as_float((unsigned)(u >> 32));
    return lo + hi;
}

#define WARP_RED_SUM(v)                                   \
  do {                                                    \
    v += __shfl_xor_sync(0xffffffffu, v, 16);             \
    v += __shfl_xor_sync(0xffffffffu, v, 8);              \
    v += __shfl_xor_sync(0xffffffffu, v, 4);              \
    v += __shfl_xor_sync(0xffffffffu, v, 2);              \
    v += __shfl_xor_sync(0xffffffffu, v, 1);              \
  } while (0)

// ---------------------------------------------------------------------------
// prep_xsum: g_xsum[b][a] = sum_m x[b][m][a].
// ---------------------------------------------------------------------------
__global__ void __launch_bounds__(256)
prep_xsum(const float* __restrict__ x)
{
    __shared__ float red[8][8];
    const int t = threadIdx.x;
    const int b = blockIdx.x;
    const int w = t >> 5, lane = t & 31;

    const float4* xs4 = (const float4*)(x + (size_t)b * 8192);
    float4 acc = make_float4(0.f, 0.f, 0.f, 0.f);
    #pragma unroll
    for (int i = 0; i < 8; i++) {
        float4 v = xs4[t + i * 256];
        acc.x += v.x; acc.y += v.y; acc.z += v.z; acc.w += v.w;
    }
    #pragma unroll
    for (int off = 2; off <= 16; off <<= 1) {
        acc.x += __shfl_xor_sync(0xffffffffu, acc.x, off);
        acc.y += __shfl_xor_sync(0xffffffffu, acc.y, off);
        acc.z += __shfl_xor_sync(0xffffffffu, acc.z, off);
        acc.w += __shfl_xor_sync(0xffffffffu, acc.w, off);
    }
    if (lane < 2) {
        red[w][lane * 4 + 0] = acc.x;
        red[w][lane * 4 + 1] = acc.y;
        red[w][lane * 4 + 2] = acc.z;
        red[w][lane * 4 + 3] = acc.w;
    }
    __syncthreads();
    if (t < 8) {
        float s = 0.f;
        #pragma unroll
        for (int i = 0; i < 8; i++) s += red[i][t];
        g_xsum[b * 8 + t] = s;
    }
}

// ---------------------------------------------------------------------------
// u0_kernel (R12, proven): iteration-0 fused (y0 from xsum, tail, agree).
// ---------------------------------------------------------------------------
#define U_THREADS 320

__global__ void __launch_bounds__(U_THREADS)
u0_kernel(const float* __restrict__ x, const float* __restrict__ W)
{
    __shared__ float wvs[16 * 160];
    __shared__ float svm[16 * 320];
    __shared__ float ysm[16 * 8];
    __shared__ float cqm[16 * 16];
    float* xsU = svm;

    const int tid   = threadIdx.x;
    const int m0    = blockIdx.x * 64;
    const int bbase = blockIdx.y * 16;

    if (tid < 128) {
        int bb = tid >> 3, a = tid & 7;
        ysm[tid] = g_xsum[(bbase + bb) * 8 + a] * (1.0f / 1024.0f);
    }
    __syncthreads();

    {
        float wreg[8];
        const float4* wp4 = (const float4*)(W + tid * 8);
        float4 wA = wp4[0], wB = wp4[1];
        wreg[0] = wA.x; wreg[1] = wA.y; wreg[2] = wA.z; wreg[3] = wA.w;
        wreg[4] = wB.x; wreg[5] = wB.y; wreg[6] = wB.z; wreg[7] = wB.w;
        #pragma unroll
        for (int bb = 0; bb < 16; bb++) {
            const float* y = ysm + bb * 8;
            float s = 0.f;
            #pragma unroll
            for (int a = 0; a < 8; a++) s += wreg[a] * y[a];
            svm[bb * 320 + tid] = s;
        }
    }
    __syncthreads();

    if (tid < 256) {
        int bb = tid >> 4, o = tid & 15;
        float msq = 0.f;
        #pragma unroll
        for (int kk = 0; kk < NK; kk++) {
            float t = svm[bb * 320 + kk * 16 + o];
            msq += t * t;
        }
        cqm[tid] = msq / ((1.f + msq) * sqrtf(msq));
    }
    __syncthreads();

    {
        const int o = tid & 15;
        #pragma unroll
        for (int bb = 0; bb < 16; bb++)
            svm[bb * 320 + tid] *= cqm[bb * 16 + o];
    }
    __syncthreads();

    {
        const int r   = tid % 160;
        const int bb0 = tid / 160;
        const int kk  = r >> 3, aa = r & 7;
        float w16[16];
        #pragma unroll
        for (int oo = 0; oo < 16; oo++) w16[oo] = W[(kk * 16 + oo) * 8 + aa];
        #pragma unroll
        for (int s8 = 0; s8 < 8; s8++) {
            int bb = bb0 + s8 * 2;
            float acc = 0.f;
            #pragma unroll
            for (int oo = 0; oo < 16; oo++)
                acc += w16[oo] * svm[bb * 320 + kk * 16 + oo];
            wvs[bb * 160 + r] = acc;
        }
    }

    const int mi4 = tid / NK;
    const int k   = tid % NK;
    unsigned long long acc[4];
    #pragma unroll
    for (int i = 0; i < 4; i++) acc[i] = 0ull;

    for (int c0 = 0; c0 < 16; c0 += 8) {
        __syncthreads();
        for (int i = tid; i < 1024; i += U_THREADS) {
            int bi = i >> 7, rr = i & 127;
            ((float4*)(xsU + bi * 512))[rr] =
                ((const float4*)(x + (size_t)(bbase + c0 + bi) * 8192 + m0 * 8))[rr];
        }
        __syncthreads();

        #pragma unroll
        for (int bi = 0; bi < 8; bi++) {
            const ulonglong2* wp = (const ulonglong2*)(wvs + (c0 + bi) * 160 + k * 8);
            ulonglong2 wA = wp[0], wB = wp[1];
            const ulonglong2* xp = (const ulonglong2*)(xsU + bi * 512 + mi4 * 32);
            #pragma unroll
            for (int mm = 0; mm < 4; mm++) {
                ulonglong2 xA = xp[mm * 2];
                ulonglong2 xB = xp[mm * 2 + 1];
                FMA2(acc[mm], xA.x, wA.x);
                FMA2(acc[mm], xA.y, wA.y);
                FMA2(acc[mm], xB.x, wB.x);
                FMA2(acc[mm], xB.y, wB.y);
            }
        }
    }

    float* dst = g_bpart + (size_t)blockIdx.y * (NK * MUL) + k * MUL + m0 + mi4 * 4;
    #pragma unroll
    for (int mm = 0; mm < 4; mm++) dst[mm] = pair_sum(acc[mm]) * (1.0f / 256.0f);
}

// ---------------------------------------------------------------------------
// Y kernel: 512 blocks = (batch, m-half), 320 threads, 3 blocks/SM.
// Stage c-half (20x512) + x-half planes (8x520) in dynamic smem;
// y-partial = c^T x over the half via (kq,ah) warps; write g_yh[b][mh][k][a].
// ---------------------------------------------------------------------------
#define Y_THREADS 320
#define PLH 520
#define Y_FLOATS (20 * 512 + 8 * PLH)     // 14400 floats = 57.6 KB

__global__ void __launch_bounds__(Y_THREADS, 3)
y_kernel(const float* __restrict__ x)
{
    extern __shared__ float sm[];
    float* cs = sm;                       // [20][512]
    float* xs = sm + 20 * 512;            // [8][PLH]

    const int tid = threadIdx.x;
    const int B = blockIdx.x;
    const int b = B >> 1, mh = B & 1;

    // stage c half: coalesced float4
    {
        const float4* csrc = (const float4*)(g_c + mh * 512);
        float4* cdst = (float4*)cs;
        #pragma unroll
        for (int i = 0; i < 8; i++) {
            int q = tid + i * Y_THREADS;          // 0..2559
            int k = q >> 7, r = q & 127;
            cdst[k * 128 + r] = csrc[k * 256 + r];
        }
    }
    // stage x half transposed to planes
    {
        const float4* xsrc = (const float4*)(x + (size_t)b * 8192 + mh * 4096);
        #pragma unroll
        for (int i = tid; i < 1024; i += Y_THREADS) {
            int m = i >> 1, half = i & 1;
            float4 v = xsrc[i];
            float* base = xs + half * 4 * PLH + m;
            base[0 * PLH] = v.x; base[1 * PLH] = v.y;
            base[2 * PLH] = v.z; base[3 * PLH] = v.w;
        }
    }
    __syncthreads();

    // y loop: 10 warps = (kq, ah); 4 classes x 4 atoms, all-SMEM operands
    const int w = tid >> 5, lane = tid & 31;
    const int k0 = (w >> 1) * 4;
    const int a0 = (w & 1) * 4;

    unsigned long long acc[4][4];
    #pragma unroll
    for (int kk = 0; kk < 4; kk++)
        #pragma unroll
        for (int aa = 0; aa < 4; aa++) acc[kk][aa] = 0ull;

    #pragma unroll 2
    for (int j = 0; j < 4; j++) {
        const int m = j * 128 + lane * 4;
        ulonglong2 ck0 = *(const ulonglong2*)(cs + (k0 + 0) * 512 + m);
        ulonglong2 ck1 = *(const ulonglong2*)(cs + (k0 + 1) * 512 + m);
        ulonglong2 ck2 = *(const ulonglong2*)(cs + (k0 + 2) * 512 + m);
        ulonglong2 ck3 = *(const ulonglong2*)(cs + (k0 + 3) * 512 + m);
        #pragma unroll
        for (int aa = 0; aa < 4; aa++) {
            ulonglong2 xv = *(const ulonglong2*)(xs + (a0 + aa) * PLH + m);
            FMA2(acc[0][aa], ck0.x, xv.x); FMA2(acc[0][aa], ck0.y, xv.y);
            FMA2(acc[1][aa], ck1.x, xv.x); FMA2(acc[1][aa], ck1.y, xv.y);
            FMA2(acc[2][aa], ck2.x, xv.x); FMA2(acc[2][aa], ck2.y, xv.y);
            FMA2(acc[3][aa], ck3.x, xv.x); FMA2(acc[3][aa], ck3.y, xv.y);
        }
    }
    #pragma unroll
    for (int kk = 0; kk < 4; kk++) {
        #pragma unroll
        for (int aa = 0; aa < 4; aa++) {
            float v = pair_sum(acc[kk][aa]);
            WARP_RED_SUM(v);
            if (lane == 0)
                g_yh[(size_t)B * 160 + (k0 + kk) * 8 + a0 + aa] = v;
        }
    }
}

// ---------------------------------------------------------------------------
// u1_kernel: like u0 but y built from g_yh halves (iterations >= 1).
// ---------------------------------------------------------------------------
__global__ void __launch_bounds__(U_THREADS)
u1_kernel(const float* __restrict__ x, const float* __restrict__ W)
{
    __shared__ float wvs[16 * 160];
    __shared__ float svm[16 * 320];
    __shared__ float ysm[16 * 160];
    __shared__ float cqm[16 * 16];
    float* xsU = svm;

    const int tid   = threadIdx.x;
    const int m0    = blockIdx.x * 64;
    const int bbase = blockIdx.y * 16;

    // y = sum of two m-half partials per batch
    for (int i = tid; i < 2560; i += U_THREADS) {
        int bb = i / 160, r = i % 160;
        size_t base = (size_t)(bbase + bb) * 2 * 160;
        ysm[i] = g_yh[base + r] + g_yh[base + 160 + r];
    }
    __syncthreads();

    // s = W y (thread = (k,o))
    {
        float wreg[8];
        const float4* wp4 = (const float4*)(W + tid * 8);
        float4 wA = wp4[0], wB = wp4[1];
        wreg[0] = wA.x; wreg[1] = wA.y; wreg[2] = wA.z; wreg[3] = wA.w;
        wreg[4] = wB.x; wreg[5] = wB.y; wreg[6] = wB.z; wreg[7] = wB.w;
        const int k = tid >> 4;
        #pragma unroll
        for (int bb = 0; bb < 16; bb++) {
            const float* y = ysm + bb * 160 + k * 8;
            float s = 0.f;
            #pragma unroll
            for (int a = 0; a < 8; a++) s += wreg[a] * y[a];
            svm[bb * 320 + tid] = s;
        }
    }
    __syncthreads();

    if (tid < 256) {
        int bb = tid >> 4, o = tid & 15;
        float msq = 0.f;
        #pragma unroll
        for (int kk = 0; kk < NK; kk++) {
            float t = svm[bb * 320 + kk * 16 + o];
            msq += t * t;
        }
        cqm[tid] = msq / ((1.f + msq) * sqrtf(msq));
    }
    __syncthreads();

    {
        const int o = tid & 15;
        #pragma unroll
        for (int bb = 0; bb < 16; bb++)
            svm[bb * 320 + tid] *= cqm[bb * 16 + o];
    }
    __syncthreads();

    {
        const int r   = tid % 160;
        const int bb0 = tid / 160;
        const int kk  = r >> 3, aa = r & 7;
        float w16[16];
        #pragma unroll
        for (int oo = 0; oo < 16; oo++) w16[oo] = W[(kk * 16 + oo) * 8 + aa];
        #pragma unroll
        for (int s8 = 0; s8 < 8; s8++) {
            int bb = bb0 + s8 * 2;
            float acc = 0.f;
            #pragma unroll
            for (int oo = 0; oo < 16; oo++)
                acc += w16[oo] * svm[bb * 320 + kk * 16 + oo];
            wvs[bb * 160 + r] = acc;
        }
    }

    const int mi4 = tid / NK;
    const int k   = tid % NK;
    unsigned long long acc[4];
    #pragma unroll
    for (int i = 0; i < 4; i++) acc[i] = 0ull;

    for (int c0 = 0; c0 < 16; c0 += 8) {
        __syncthreads();
        for (int i = tid; i < 1024; i += U_THREADS) {
            int bi = i >> 7, rr = i & 127;
            ((float4*)(xsU + bi * 512))[rr] =
                ((const float4*)(x + (size_t)(bbase + c0 + bi) * 8192 + m0 * 8))[rr];
        }
        __syncthreads();

        #pragma unroll
        for (int bi = 0; bi < 8; bi++) {
            const ulonglong2* wp = (const ulonglong2*)(wvs + (c0 + bi) * 160 + k * 8);
            ulonglong2 wA = wp[0], wB = wp[1];
            const ulonglong2* xp = (const ulonglong2*)(xsU + bi * 512 + mi4 * 32);
            #pragma unroll
            for (int mm = 0; mm < 4; mm++) {
                ulonglong2 xA = xp[mm * 2];
                ulonglong2 xB = xp[mm * 2 + 1];
                FMA2(acc[mm], xA.x, wA.x);
                FMA2(acc[mm], xA.y, wA.y);
                FMA2(acc[mm], xB.x, wB.x);
                FMA2(acc[mm], xB.y, wB.y);
            }
        }
    }

    float* dst = g_bpart + (size_t)blockIdx.y * (NK * MUL) + k * MUL + m0 + mi4 * 4;
    #pragma unroll
    for (int mm = 0; mm < 4; mm++) dst[mm] = pair_sum(acc[mm]) * (1.0f / 256.0f);
}

// ---------------------------------------------------------------------------
// out_kernel: final tail from g_yh halves -> output. 256 blocks x 320 threads.
// ---------------------------------------------------------------------------
__global__ void __launch_bounds__(320)
out_kernel(const float* __restrict__ W, float* __restrict__ out)
{
    __shared__ float ysm[NK * AIN];
    __shared__ float svm[NK * NO];
    __shared__ float cqm[NO];
    const int tid = threadIdx.x;
    const int b   = blockIdx.x;

    if (tid < 160) {
        size_t base = (size_t)b * 2 * 160;
        ysm[tid] = g_yh[base + tid] + g_yh[base + 160 + tid];
    }
    __syncthreads();

    const int k = tid >> 4, o = tid & 15;
    float s = 0.f;
    #pragma unroll
    for (int a = 0; a < 8; a++) s += W[tid * 8 + a] * ysm[k * 8 + a];
    svm[tid] = s;
    __syncthreads();

    if (tid < NO) {
        float msq = 0.f;
        #pragma unroll
        for (int kk = 0; kk < NK; kk++) {
            float t = svm[kk * NO + tid];
            msq += t * t;
        }
        cqm[tid] = msq / ((1.f + msq) * sqrtf(msq));
    }
    __syncthreads();

    out[(size_t)b * 320 + tid] = cqm[o] * s;
}

// ---------------------------------------------------------------------------
// Softmax kernel (no max subtraction; inputs bounded, fp32-safe).
// ---------------------------------------------------------------------------
__global__ void __launch_bounds__(1024)
softmax_kernel(int accum)
{
    const int k = blockIdx.x;
    const int t = threadIdx.x;
    const int lane = t & 31, wp = t >> 5;
    __shared__ float red[32];
    __shared__ float bc;

    float b = accum ? g_b[k * MUL + t] : 0.f;
    #pragma unroll
    for (int p = 0; p < 16; p++) b += g_bpart[p * NK * MUL + k * MUL + t];
    g_b[k * MUL + t] = b;

    float e = expf(b);
    float s = e;
    #pragma unroll
    for (int off = 16; off; off >>= 1)
        s += __shfl_xor_sync(0xffffffffu, s, off);
    if (lane == 0) red[wp] = s;
    __syncthreads();
    if (t < 32) {
        float ss = red[t];
        #pragma unroll
        for (int off = 16; off; off >>= 1)
            ss += __shfl_xor_sync(0xffffffffu, ss, off);
        if (t == 0) bc = ss;
    }
    __syncthreads();

    g_c[k * MUL + t] = e * (1.0f / bc);
}

// ---------------------------------------------------------------------------
extern "C" void kernel_launch(void* const* d_in, const int* in_sizes, int n_in,
                              void* d_out, int out_size)
{
    const float* x = (const float*)d_in[0];   // [256][1024][8] flat view
    const float* W = (const float*)d_in[1];   // [20][16][8]
    float* out = (float*)d_out;               // [256][20][16][1]

    const int Y_SMEM = Y_FLOATS * (int)sizeof(float);   // 57.6 KB dynamic
    cudaFuncSetAttribute(y_kernel,
                         cudaFuncAttributeMaxDynamicSharedMemorySize, Y_SMEM);

    dim3 ugrid(16, 16);

    // iteration 0: xsum -> (y0 + tail + agree) -> softmax
    prep_xsum<<<B_TOT, 256>>>(x);
    u0_kernel<<<ugrid, U_THREADS>>>(x, W);
    softmax_kernel<<<NK, 1024>>>(0);

    // iteration 1: y partials -> (combine + tail + agree) -> softmax
    y_kernel<<<512, Y_THREADS, Y_SMEM>>>(x);
    u1_kernel<<<ugrid, U_THREADS>>>(x, W);
    softmax_kernel<<<NK, 1024>>>(1);

    // iteration 2 (final): y partials -> output
    y_kernel<<<512, Y_THREADS, Y_SMEM>>>(x);
    out_kernel<<<B_TOT, 320>>>(W, out);
}